// round 11
// baseline (speedup 1.0000x reference)
#include <cuda_runtime.h>
#include <math.h>

#define BB   128
#define SS   400
#define EE   512
#define TT   300
#define VV   30
#define EMBD 256
#define H1   512
#define H2   128
#define PP   128
#define G1   2048
#define G2   512
#define NCTA 128
#define NTHR 256
#define PRED_N (BB*VV*TT)

// ---------------- device scratch (no cudaMalloc allowed) ----------------
__device__ float g_keys  [BB*SS*PP];
__device__ float g_values[BB*SS*PP];
__device__ float g_W1t   [640*G1];     // [k][j] packed: k<128 ctx part of W_ih1, else W_hh1
__device__ float g_W2t   [H1*G2];      // [k][j] = W_ih2[j][k]
__device__ float g_Memb  [VV*G1];      // emb contribution + b_ih1 + b_hh1
__device__ float g_part1 [2][BB*G1];   // LSTM1 gate partials (k-split 2)
__device__ float g_g2base[BB*G2];      // LSTM2 gates: h2 part + biases
__device__ float g_g2p   [8][BB*G2];   // LSTM2 gates: h1 part partials (k-split 8)
__device__ float g_h1[BB*H1], g_c1[BB*H1];
__device__ float g_h2[BB*H2], g_c2[BB*H2], g_ctx[BB*PP];
__device__ unsigned g_barcnt;
__device__ volatile unsigned g_bargen;

__device__ __forceinline__ float sigf(float x) { return 1.f / (1.f + expf(-x)); }

__device__ __forceinline__ void fma16(float4& a0, float4& a1, float4& a2, float4& a3,
                                      float4 xv, float4 wv) {
    a0.x += xv.x*wv.x; a0.y += xv.x*wv.y; a0.z += xv.x*wv.z; a0.w += xv.x*wv.w;
    a1.x += xv.y*wv.x; a1.y += xv.y*wv.y; a1.z += xv.y*wv.z; a1.w += xv.y*wv.w;
    a2.x += xv.z*wv.x; a2.y += xv.z*wv.y; a2.z += xv.z*wv.z; a2.w += xv.z*wv.w;
    a3.x += xv.w*wv.x; a3.y += xv.w*wv.y; a3.z += xv.w*wv.z; a3.w += xv.w*wv.w;
}

// ---------------- grid-wide software barrier (all 128 CTAs resident) ----------------
__device__ __forceinline__ void gridbar() {
    __syncthreads();
    if (threadIdx.x == 0) {
        __threadfence();
        unsigned g = g_bargen;
        if (atomicAdd(&g_barcnt, 1u) == (NCTA - 1u)) {
            g_barcnt = 0u;
            __threadfence();
            g_bargen = g + 1u;
        } else {
            while (g_bargen == g) { }
        }
        __threadfence();
    }
    __syncthreads();
}

// ---------------- precompute kernels ----------------
__global__ void pack_kernel(const float* __restrict__ Wih1, const float* __restrict__ Whh1,
                            const float* __restrict__ Wih2) {
    int gid = blockIdx.x * blockDim.x + threadIdx.x;
    if (gid < 640 * G1) {
        int k = gid / G1, j = gid % G1;
        g_W1t[gid] = (k < PP) ? Wih1[j * (EMBD + PP) + k] : Whh1[j * H1 + (k - PP)];
    } else {
        int g2 = gid - 640 * G1;
        if (g2 < H1 * G2) {
            int k = g2 / G2, j = g2 % G2;
            g_W2t[g2] = Wih2[j * H1 + k];
        }
    }
}

__global__ void memb_kernel(const float* __restrict__ emb, const float* __restrict__ Wih1,
                            const float* __restrict__ bih1, const float* __restrict__ bhh1) {
    int gid = blockIdx.x * blockDim.x + threadIdx.x;
    if (gid >= VV * G1) return;
    int v = gid / G1, j = gid % G1;
    const float* er = emb + v * EMBD;
    const float* wr = Wih1 + j * (EMBD + PP) + PP;   // emb part of x
    float s = bih1[j] + bhh1[j];
    for (int k = 0; k < EMBD; k++) s += er[k] * wr[k];
    g_Memb[gid] = s;
}

// keys/values: out[row][p] = enc[row] . W[p] + bias[p], rows = B*S = 51200, K = 512
__global__ __launch_bounds__(256) void kv_kernel(
    const float* __restrict__ enc,
    const float* __restrict__ Wk, const float* __restrict__ bk,
    const float* __restrict__ Wv, const float* __restrict__ bv) {
    __shared__ float sh[10752];
    float* xs = sh;          // [64][132]
    float* ws = sh + 8448;   // [64][36]
    int rt = blockIdx.x;                 // 0..399
    int m = blockIdx.y;                  // 0..7
    int mat = m >> 2, jt = m & 3;
    const float* W    = mat ? Wv : Wk;
    const float* bias = mat ? bv : bk;
    float* out        = mat ? g_values : g_keys;
    int r0 = rt * 128, j0 = jt * 32;
    int tid = threadIdx.x;
    int tb = tid >> 3, tj = tid & 7;
    float4 a0 = {0,0,0,0}, a1 = a0, a2 = a0, a3 = a0;
    for (int kc = 0; kc < EE; kc += 64) {
        #pragma unroll
        for (int i = 0; i < 32; i++) {
            int lin = i * 256 + tid;
            int br = lin >> 6, kk = lin & 63;
            xs[kk * 132 + br] = enc[(size_t)(r0 + br) * EE + kc + kk];
        }
        #pragma unroll
        for (int i = 0; i < 8; i++) {
            int lin = i * 256 + tid;
            int jj = lin >> 6, kk = lin & 63;
            ws[kk * 36 + jj] = W[(j0 + jj) * EE + kc + kk];
        }
        __syncthreads();
        #pragma unroll 16
        for (int kk = 0; kk < 64; kk++) {
            float4 xv = *(const float4*)&xs[kk * 132 + tb * 4];
            float4 wv = *(const float4*)&ws[kk * 36 + tj * 4];
            fma16(a0, a1, a2, a3, xv, wv);
        }
        __syncthreads();
    }
    float4 bb = *(const float4*)&bias[j0 + tj * 4];
    a0.x += bb.x; a0.y += bb.y; a0.z += bb.z; a0.w += bb.w;
    a1.x += bb.x; a1.y += bb.y; a1.z += bb.z; a1.w += bb.w;
    a2.x += bb.x; a2.y += bb.y; a2.z += bb.z; a2.w += bb.w;
    a3.x += bb.x; a3.y += bb.y; a3.z += bb.z; a3.w += bb.w;
    int co = j0 + tj * 4;
    *(float4*)&out[(size_t)(r0 + tb * 4 + 0) * PP + co] = a0;
    *(float4*)&out[(size_t)(r0 + tb * 4 + 1) * PP + co] = a1;
    *(float4*)&out[(size_t)(r0 + tb * 4 + 2) * PP + co] = a2;
    *(float4*)&out[(size_t)(r0 + tb * 4 + 3) * PP + co] = a3;
}

// zero states + context0 = mean_s(values)
__global__ void init_kernel() {
    int gid = blockIdx.x * blockDim.x + threadIdx.x;   // 65536 threads
    if (gid < BB * H1) { g_h1[gid] = 0.f; g_c1[gid] = 0.f; }
    if (gid < BB * H2) {
        g_h2[gid] = 0.f; g_c2[gid] = 0.f;
        int b = gid >> 7, p = gid & 127;
        float s = 0.f;
        for (int ss = 0; ss < SS; ss++) s += g_values[((size_t)b * SS + ss) * PP + p];
        g_ctx[gid] = s * (1.f / SS);
    }
}

// ---------------- the persistent decode loop ----------------
__global__ __launch_bounds__(NTHR, 1) void loop_kernel(
    const int* __restrict__ y, const int* __restrict__ lens,
    const float* __restrict__ Wq, const float* __restrict__ bq,
    const float* __restrict__ Whh2, const float* __restrict__ bih2, const float* __restrict__ bhh2,
    const float* __restrict__ emb, const float* __restrict__ bout,
    float* __restrict__ out) {
    __shared__ float sh[10752];
    int cta = blockIdx.x;
    int tid = threadIdx.x;
    int gid = cta * NTHR + tid;

    for (int t = 0; t < TT; t++) {
        // ---- Stage A: LSTM1 gate GEMM (x = [ctx|h1], K=640, 2-way k-split) ----
        {
            float* xs = sh;          // [64][132]
            float* ws = sh + 8448;   // [64][32]
            int jt = cta >> 1, kh = cta & 1;
            int j0 = jt * 32, kb = kh * 320;
            int tb = tid >> 3, tj = tid & 7;
            float4 a0 = {0,0,0,0}, a1 = a0, a2 = a0, a3 = a0;
            for (int kc = 0; kc < 320; kc += 64) {
                #pragma unroll
                for (int i = 0; i < 32; i++) {
                    int lin = i * 256 + tid;
                    int br = lin >> 6, kk = lin & 63;
                    int k = kb + kc + kk;
                    xs[kk * 132 + br] = (k < PP) ? g_ctx[br * PP + k]
                                                 : g_h1[br * H1 + (k - PP)];
                }
                #pragma unroll
                for (int i = 0; i < 8; i++) {
                    int lin = i * 256 + tid;
                    int kk = lin >> 5, jj = lin & 31;
                    ws[kk * 32 + jj] = g_W1t[(kb + kc + kk) * G1 + j0 + jj];
                }
                __syncthreads();
                #pragma unroll 16
                for (int kk = 0; kk < 64; kk++) {
                    float4 xv = *(const float4*)&xs[kk * 132 + tb * 4];
                    float4 wv = *(const float4*)&ws[kk * 32 + tj * 4];
                    fma16(a0, a1, a2, a3, xv, wv);
                }
                __syncthreads();
            }
            float* dst = g_part1[kh];
            int co = j0 + tj * 4;
            *(float4*)&dst[(tb * 4 + 0) * G1 + co] = a0;
            *(float4*)&dst[(tb * 4 + 1) * G1 + co] = a1;
            *(float4*)&dst[(tb * 4 + 2) * G1 + co] = a2;
            *(float4*)&dst[(tb * 4 + 3) * G1 + co] = a3;
        }
        gridbar();

        // ---- Stage B: LSTM1 cell update + LSTM2 gate base (h2_{t-1} part + biases) ----
        {
            for (int idx = gid; idx < BB * H1; idx += NCTA * NTHR) {
                int b = idx >> 9, h = idx & (H1 - 1);
                int tok = (t == 0) ? 0 : y[b * TT + t];
                int base = b * G1;
                const float* mrow = g_Memb + tok * G1;
                float gi = g_part1[0][base + h]        + g_part1[1][base + h]        + mrow[h];
                float gf = g_part1[0][base + 512 + h]  + g_part1[1][base + 512 + h]  + mrow[512 + h];
                float gg = g_part1[0][base + 1024 + h] + g_part1[1][base + 1024 + h] + mrow[1024 + h];
                float go = g_part1[0][base + 1536 + h] + g_part1[1][base + 1536 + h] + mrow[1536 + h];
                float c = sigf(gf) * g_c1[idx] + sigf(gi) * tanhf(gg);
                g_c1[idx] = c;
                g_h1[idx] = sigf(go) * tanhf(c);
            }
            for (int idx = gid; idx < BB * G2; idx += NCTA * NTHR) {
                int b = idx >> 9, j = idx & (G2 - 1);
                const float4* h2r = (const float4*)(g_h2 + b * H2);
                const float4* wr  = (const float4*)(Whh2 + j * H2);
                float s = bih2[j] + bhh2[j];
                #pragma unroll 8
                for (int k4 = 0; k4 < 32; k4++) {
                    float4 h4 = h2r[k4], w4 = wr[k4];
                    s += h4.x*w4.x + h4.y*w4.y + h4.z*w4.z + h4.w*w4.w;
                }
                g_g2base[idx] = s;
            }
        }
        gridbar();

        // ---- Stage B2: LSTM2 gate GEMM h1 part (K=512, 8-way k-split) ----
        {
            float* xs = sh;
            float* ws = sh + 8448;
            int jt = cta >> 3, ks = cta & 7;
            int j0 = jt * 32, k0 = ks * 64;
            int tb = tid >> 3, tj = tid & 7;
            float4 a0 = {0,0,0,0}, a1 = a0, a2 = a0, a3 = a0;
            #pragma unroll
            for (int i = 0; i < 32; i++) {
                int lin = i * 256 + tid;
                int br = lin >> 6, kk = lin & 63;
                xs[kk * 132 + br] = g_h1[br * H1 + k0 + kk];
            }
            #pragma unroll
            for (int i = 0; i < 8; i++) {
                int lin = i * 256 + tid;
                int kk = lin >> 5, jj = lin & 31;
                ws[kk * 32 + jj] = g_W2t[(k0 + kk) * G2 + j0 + jj];
            }
            __syncthreads();
            #pragma unroll 16
            for (int kk = 0; kk < 64; kk++) {
                float4 xv = *(const float4*)&xs[kk * 132 + tb * 4];
                float4 wv = *(const float4*)&ws[kk * 32 + tj * 4];
                fma16(a0, a1, a2, a3, xv, wv);
            }
            __syncthreads();
            float* dst = g_g2p[ks];
            int co = j0 + tj * 4;
            *(float4*)&dst[(tb * 4 + 0) * G2 + co] = a0;
            *(float4*)&dst[(tb * 4 + 1) * G2 + co] = a1;
            *(float4*)&dst[(tb * 4 + 2) * G2 + co] = a2;
            *(float4*)&dst[(tb * 4 + 3) * G2 + co] = a3;
        }
        gridbar();

        // ---- Stage C: per-batch CTA: LSTM2 cell, q, attention, context, logits ----
        {
            int b = cta;
            float* sg   = sh;            // 512
            float* h2s  = sh + 512;      // 128
            float* qs   = sh + 640;      // 128 (reused as ctx)
            float* satt = sh + 768;      // 400
            float* red  = sh + 1200;     // 256
            float* cred = sh + 1456;     // 256
            float* sinv = sh + 1712;     // 1

            for (int j = tid; j < G2; j += NTHR) {
                float s = g_g2base[b * G2 + j];
                #pragma unroll
                for (int ks = 0; ks < 8; ks++) s += g_g2p[ks][b * G2 + j];
                sg[j] = s;
            }
            __syncthreads();
            if (tid < H2) {
                int h = tid;
                float c = sigf(sg[128 + h]) * g_c2[b * H2 + h] + sigf(sg[h]) * tanhf(sg[256 + h]);
                g_c2[b * H2 + h] = c;
                float hh = sigf(sg[384 + h]) * tanhf(c);
                g_h2[b * H2 + h] = hh;
                h2s[h] = hh;
            }
            __syncthreads();
            if (tid < PP) {
                const float* wr = Wq + tid * H2;
                float s = bq[tid];
                for (int k = 0; k < H2; k++) s += h2s[k] * wr[k];
                qs[tid] = s;
            }
            __syncthreads();
            int lenb = lens[b];
            const float scale = 0.08838834764831845f;   // 1/sqrt(128)
            float pmax = -3.4e38f;
            for (int s = tid; s < SS; s += NTHR) {
                const float4* kr = (const float4*)(g_keys + ((size_t)b * SS + s) * PP);
                const float4* q4 = (const float4*)qs;
                float d = 0.f;
                #pragma unroll 8
                for (int p4 = 0; p4 < 32; p4++) {
                    float4 kv = kr[p4], qv = q4[p4];
                    d += kv.x*qv.x + kv.y*qv.y + kv.z*qv.z + kv.w*qv.w;
                }
                d *= scale;
                if (s >= lenb) d = -1e9f;
                satt[s] = d;
                pmax = fmaxf(pmax, d);
            }
            red[tid] = pmax; __syncthreads();
            for (int o = 128; o > 0; o >>= 1) {
                if (tid < o) red[tid] = fmaxf(red[tid], red[tid + o]);
                __syncthreads();
            }
            float mx = red[0];
            __syncthreads();
            float psum = 0.f;
            for (int s = tid; s < SS; s += NTHR) {
                float e = expf(satt[s] - mx);
                satt[s] = e;
                psum += e;
            }
            red[tid] = psum; __syncthreads();
            for (int o = 128; o > 0; o >>= 1) {
                if (tid < o) red[tid] += red[tid + o];
                __syncthreads();
            }
            if (tid == 0) sinv[0] = 1.f / red[0];
            __syncthreads();
            float inv = sinv[0];
            {
                int p = tid & 127, half = tid >> 7;
                float c = 0.f;
                int s0 = half * 200;
                for (int s = s0; s < s0 + 200; s++)
                    c += satt[s] * g_values[((size_t)b * SS + s) * PP + p];
                cred[tid] = c;
            }
            __syncthreads();
            if (tid < PP) {
                float c = (cred[tid] + cred[tid + 128]) * inv;
                g_ctx[b * PP + tid] = c;
                qs[tid] = c;   // reuse as context smem
            }
            __syncthreads();
            if (tid < VV) {
                const float* er = emb + tid * EMBD;
                float lg = bout[tid];
                for (int e = 0; e < 128; e++) lg += qs[e] * er[e] + h2s[e] * er[128 + e];
                out[((size_t)b * VV + tid) * TT + t] = lg;   // predictions [B,V,T]
            }
            if (b == 0) {
                for (int s = tid; s < SS; s += NTHR)
                    out[PRED_N + t * SS + s] = satt[s] * inv;  // attention_plot [T,S]
            }
        }
        gridbar();
    }
}

// ---------------- launch ----------------
extern "C" void kernel_launch(void* const* d_in, const int* in_sizes, int n_in,
                              void* d_out, int out_size) {
    (void)in_sizes; (void)n_in; (void)out_size;
    const float* enc  = (const float*)d_in[0];
    const int*   lens = (const int*)d_in[1];
    const int*   y    = (const int*)d_in[2];
    const float* emb  = (const float*)d_in[3];
    const float* Wih1 = (const float*)d_in[4];
    const float* Whh1 = (const float*)d_in[5];
    const float* bih1 = (const float*)d_in[6];
    const float* bhh1 = (const float*)d_in[7];
    const float* Wih2 = (const float*)d_in[8];
    const float* Whh2 = (const float*)d_in[9];
    const float* bih2 = (const float*)d_in[10];
    const float* bhh2 = (const float*)d_in[11];
    const float* Wk   = (const float*)d_in[12];
    const float* bk   = (const float*)d_in[13];
    const float* Wv   = (const float*)d_in[14];
    const float* bv   = (const float*)d_in[15];
    const float* Wq   = (const float*)d_in[16];
    const float* bq   = (const float*)d_in[17];
    const float* bout = (const float*)d_in[18];
    float* out = (float*)d_out;

    pack_kernel<<<(640 * G1 + H1 * G2 + 255) / 256, 256>>>(Wih1, Whh1, Wih2);
    memb_kernel<<<(VV * G1 + 255) / 256, 256>>>(emb, Wih1, bih1, bhh1);
    kv_kernel<<<dim3(400, 8), 256>>>(enc, Wk, bk, Wv, bv);
    init_kernel<<<256, 256>>>();
    loop_kernel<<<NCTA, NTHR>>>(y, lens, Wq, bq, Whh2, bih2, bhh2, emb, bout, out);
}

// round 13
// speedup vs baseline: 1.1843x; 1.1843x over previous
#include <cuda_runtime.h>
#include <math.h>

#define BB   128
#define SS   400
#define EE   512
#define TT   300
#define VV   30
#define EMBD 256
#define H1   512
#define H2   128
#define PP   128
#define G1   2048
#define G2   512
#define NCTA 128
#define NTHR 256
#define PRED_N (BB*VV*TT)

typedef unsigned long long u64;

// ---------------- device scratch (no cudaMalloc allowed) ----------------
__device__ __align__(16) float g_keys  [BB*SS*PP];
__device__ __align__(16) float g_values[BB*SS*PP];
__device__ __align__(16) float g_W1t   [640*G1];     // [k][j]: k<128 ctx cols of W_ih1, else W_hh1
__device__ __align__(16) float g_W2e   [640*G2];     // [k][j]: k<512 W_ih2, else W_hh2
__device__ __align__(16) float g_MembT [G1*32];      // [j][tok]: emb contribution + b_ih1 + b_hh1
__device__ __align__(16) float g_b2    [G2];         // b_ih2 + b_hh2
__device__ __align__(16) float g_part1 [8][G1*BB];   // LSTM1 gate partials, [ks][j][b]
__device__ __align__(16) float g_part2 [16][G2*BB];  // LSTM2 gate partials, [ks][j][b]
__device__ __align__(16) float g_xT    [768*BB];     // [k][b]: 0-127 ctx, 128-639 h1, 640-767 h2prev
__device__ __align__(16) float g_c1T   [H1*BB];      // [h][b]
__device__ __align__(16) float g_c2    [BB*H2];      // [b][h]
__device__ volatile unsigned g_flags[NCTA*32];

__device__ __forceinline__ float sigf(float x) { return 1.f / (1.f + expf(-x)); }

__device__ __forceinline__ u64 ffma2(u64 a, u64 b, u64 c) {
    u64 d; asm("fma.rn.f32x2 %0,%1,%2,%3;" : "=l"(d) : "l"(a), "l"(b), "l"(c)); return d;
}
__device__ __forceinline__ u64 pack2(float v) {
    u64 d; asm("mov.b64 %0,{%1,%1};" : "=l"(d) : "f"(v)); return d;
}

__device__ __forceinline__ void fma16(float4& a0, float4& a1, float4& a2, float4& a3,
                                      float4 xv, float4 wv) {
    a0.x += xv.x*wv.x; a0.y += xv.x*wv.y; a0.z += xv.x*wv.z; a0.w += xv.x*wv.w;
    a1.x += xv.y*wv.x; a1.y += xv.y*wv.y; a1.z += xv.y*wv.z; a1.w += xv.y*wv.w;
    a2.x += xv.z*wv.x; a2.y += xv.z*wv.y; a2.z += xv.z*wv.z; a2.w += xv.z*wv.w;
    a3.x += xv.w*wv.x; a3.y += xv.w*wv.y; a3.z += xv.w*wv.z; a3.w += xv.w*wv.w;
}

// ---------------- grid barrier: per-CTA flags, parallel poll, replay-safe epoch ----------------
__device__ __forceinline__ void gridbar(int cta, int tid, unsigned& epoch) {
    epoch++;
    __syncthreads();
    if (tid == 0) { __threadfence(); g_flags[cta * 32] = epoch; }
    if (tid < NCTA) { while (g_flags[tid * 32] < epoch) { } }
    __syncthreads();
    if (tid == 0) __threadfence();   // gpu-scope fence -> drop stale L1 lines
    __syncthreads();
}

// ---------------- precompute kernels ----------------
__global__ void pack_kernel(const float* __restrict__ Wih1, const float* __restrict__ Whh1,
                            const float* __restrict__ Wih2, const float* __restrict__ Whh2,
                            const float* __restrict__ bih2, const float* __restrict__ bhh2) {
    int gid = blockIdx.x * blockDim.x + threadIdx.x;
    if (gid < 640 * G1) {
        int k = gid / G1, j = gid % G1;
        g_W1t[gid] = (k < PP) ? Wih1[j * (EMBD + PP) + k] : Whh1[j * H1 + (k - PP)];
    } else if (gid < 640 * G1 + 640 * G2) {
        int g2 = gid - 640 * G1;
        int k = g2 / G2, j = g2 % G2;
        g_W2e[g2] = (k < H1) ? Wih2[j * H1 + k] : Whh2[j * H2 + (k - H1)];
    } else {
        int g3 = gid - 640 * G1 - 640 * G2;
        if (g3 < G2) g_b2[g3] = bih2[g3] + bhh2[g3];
    }
}

__global__ void memb_kernel(const float* __restrict__ emb, const float* __restrict__ Wih1,
                            const float* __restrict__ bih1, const float* __restrict__ bhh1) {
    int gid = blockIdx.x * blockDim.x + threadIdx.x;
    if (gid >= VV * G1) return;
    int v = gid / G1, j = gid % G1;
    const float* er = emb + v * EMBD;
    const float* wr = Wih1 + j * (EMBD + PP) + PP;   // emb part of x
    float s = bih1[j] + bhh1[j];
    for (int k = 0; k < EMBD; k++) s += er[k] * wr[k];
    g_MembT[j * 32 + v] = s;
}

// keys/values: out[row][p] = enc[row] . W[p] + bias[p], rows = B*S = 51200, K = 512
__global__ __launch_bounds__(256) void kv_kernel(
    const float* __restrict__ enc,
    const float* __restrict__ Wk, const float* __restrict__ bk,
    const float* __restrict__ Wv, const float* __restrict__ bv) {
    __shared__ float sh[10752];
    float* xs = sh;          // [64][132]
    float* ws = sh + 8448;   // [64][36]
    int rt = blockIdx.x;
    int m = blockIdx.y;
    int mat = m >> 2, jt = m & 3;
    const float* W    = mat ? Wv : Wk;
    const float* bias = mat ? bv : bk;
    float* out        = mat ? g_values : g_keys;
    int r0 = rt * 128, j0 = jt * 32;
    int tid = threadIdx.x;
    int tb = tid >> 3, tj = tid & 7;
    float4 a0 = {0,0,0,0}, a1 = a0, a2 = a0, a3 = a0;
    for (int kc = 0; kc < EE; kc += 64) {
        #pragma unroll
        for (int i = 0; i < 32; i++) {
            int lin = i * 256 + tid;
            int br = lin >> 6, kk = lin & 63;
            xs[kk * 132 + br] = enc[(size_t)(r0 + br) * EE + kc + kk];
        }
        #pragma unroll
        for (int i = 0; i < 8; i++) {
            int lin = i * 256 + tid;
            int jj = lin >> 6, kk = lin & 63;
            ws[kk * 36 + jj] = W[(j0 + jj) * EE + kc + kk];
        }
        __syncthreads();
        #pragma unroll 16
        for (int kk = 0; kk < 64; kk++) {
            float4 xv = *(const float4*)&xs[kk * 132 + tb * 4];
            float4 wv = *(const float4*)&ws[kk * 36 + tj * 4];
            fma16(a0, a1, a2, a3, xv, wv);
        }
        __syncthreads();
    }
    float4 bb = *(const float4*)&bias[j0 + tj * 4];
    a0.x += bb.x; a0.y += bb.y; a0.z += bb.z; a0.w += bb.w;
    a1.x += bb.x; a1.y += bb.y; a1.z += bb.z; a1.w += bb.w;
    a2.x += bb.x; a2.y += bb.y; a2.z += bb.z; a2.w += bb.w;
    a3.x += bb.x; a3.y += bb.y; a3.z += bb.z; a3.w += bb.w;
    int co = j0 + tj * 4;
    *(float4*)&out[(size_t)(r0 + tb * 4 + 0) * PP + co] = a0;
    *(float4*)&out[(size_t)(r0 + tb * 4 + 1) * PP + co] = a1;
    *(float4*)&out[(size_t)(r0 + tb * 4 + 2) * PP + co] = a2;
    *(float4*)&out[(size_t)(r0 + tb * 4 + 3) * PP + co] = a3;
}

// zero states, context0 = mean_s(values) into xT rows 0-127
__global__ void init_kernel() {
    int gid = blockIdx.x * blockDim.x + threadIdx.x;   // 81920 threads
    if (gid < 640 * BB) g_xT[128 * BB + gid] = 0.f;    // h1 + h2prev rows
    if (gid < H1 * BB)  g_c1T[gid] = 0.f;
    if (gid < BB * H2)  g_c2[gid] = 0.f;
    if (gid < BB * PP) {
        int b = gid >> 7, p = gid & 127;
        float s = 0.f;
        for (int ss = 0; ss < SS; ss++) s += g_values[((size_t)b * SS + ss) * PP + p];
        g_xT[p * BB + b] = s * (1.f / SS);
    }
}

// ---------------- the persistent decode loop ----------------
__global__ __launch_bounds__(NTHR, 1) void loop_kernel(
    const int* __restrict__ y, const int* __restrict__ lens,
    const float* __restrict__ Wq, const float* __restrict__ bq,
    const float* __restrict__ emb, const float* __restrict__ bout,
    float* __restrict__ out) {
    __align__(16) __shared__ float sh[4608];
    const int cta = blockIdx.x;
    const int tid = threadIdx.x;
    unsigned epoch = g_flags[cta * 32];   // persisted base -> replay-safe

    for (int t = 0; t < TT; t++) {
        // ---- Stage A: LSTM1 gates out1[j][b] = sum_k xT[k][b]*W1t[k][j], K=640, 8-way split ----
        {
            float* xs = sh;            // [16][128] = 2048
            float* ws = sh + 2048;     // [16][128] = 2048 (fits: 4096 <= 4608)
            const int rg = tid & 15, jg = tid >> 4;
            const int r0 = rg * 8, cA = jg * 8;
            const int jt = cta >> 3, ks = cta & 7;
            const int j0 = jt * 128, kb = ks * 80;
            u64 acc[4][8];
            #pragma unroll
            for (int i = 0; i < 4; i++)
                #pragma unroll
                for (int c = 0; c < 8; c++) acc[i][c] = 0ull;
            for (int kc = 0; kc < 80; kc += 16) {
                #pragma unroll
                for (int i = 0; i < 8; i++) {
                    int lin = i * 256 + tid;
                    int kk = lin >> 7, x = lin & 127;
                    xs[kk * 128 + x] = g_xT[(kb + kc + kk) * BB + x];
                    ws[kk * 128 + x] = g_W1t[(size_t)(kb + kc + kk) * G1 + j0 + x];
                }
                __syncthreads();
                #pragma unroll
                for (int kk = 0; kk < 16; kk++) {
                    ulonglong2 xa = *(const ulonglong2*)&xs[kk * 128 + r0];
                    ulonglong2 xb = *(const ulonglong2*)&xs[kk * 128 + r0 + 4];
                    float4 wA = *(const float4*)&ws[kk * 128 + cA];
                    float4 wB = *(const float4*)&ws[kk * 128 + cA + 4];
                    u64 w[8] = {pack2(wA.x), pack2(wA.y), pack2(wA.z), pack2(wA.w),
                                pack2(wB.x), pack2(wB.y), pack2(wB.z), pack2(wB.w)};
                    u64 xr[4] = {xa.x, xa.y, xb.x, xb.y};
                    #pragma unroll
                    for (int i = 0; i < 4; i++)
                        #pragma unroll
                        for (int c = 0; c < 8; c++) acc[i][c] = ffma2(xr[i], w[c], acc[i][c]);
                }
                __syncthreads();
            }
            float* dst = g_part1[ks];
            #pragma unroll
            for (int c = 0; c < 8; c++) {
                *(ulonglong2*)&dst[(size_t)(j0 + cA + c) * BB + r0]     = make_ulonglong2(acc[0][c], acc[1][c]);
                *(ulonglong2*)&dst[(size_t)(j0 + cA + c) * BB + r0 + 4] = make_ulonglong2(acc[2][c], acc[3][c]);
            }
        }
        gridbar(cta, tid, epoch);

        // ---- Stage B: LSTM1 cell update, h1 -> xT rows 128-639 ----
        {
            int* stok = (int*)(sh + 4352);   // 128 ints, past all other usage
            if (tid < BB) stok[tid] = (t == 0) ? 0 : y[tid * TT + t];
            __syncthreads();
            #pragma unroll
            for (int e = 0; e < 2; e++) {
                int idx = cta * 512 + e * 256 + tid;
                int h = idx >> 7, b = idx & 127;
                int tok = stok[b];
                float gi = g_MembT[(size_t)h * 32 + tok];
                float gf = g_MembT[(size_t)(512 + h) * 32 + tok];
                float gg = g_MembT[(size_t)(1024 + h) * 32 + tok];
                float go = g_MembT[(size_t)(1536 + h) * 32 + tok];
                #pragma unroll
                for (int ks = 0; ks < 8; ks++) {
                    const float* p = g_part1[ks];
                    gi += p[(size_t)h * BB + b];
                    gf += p[(size_t)(512 + h) * BB + b];
                    gg += p[(size_t)(1024 + h) * BB + b];
                    go += p[(size_t)(1536 + h) * BB + b];
                }
                float c = sigf(gf) * g_c1T[h * BB + b] + sigf(gi) * tanhf(gg);
                g_c1T[h * BB + b] = c;
                g_xT[(128 + h) * BB + b] = sigf(go) * tanhf(c);
            }
        }
        gridbar(cta, tid, epoch);

        // ---- Stage B2: LSTM2 gates over x2=[h1;h2prev] (xT rows 128-767), K=640, 16-way split ----
        {
            float* xs = sh;            // [20][128] = 2560
            float* ws = sh + 2560;     // [20][64]  = 1280 (total 3840 <= 4608)
            const int rg = tid & 15, jg = tid >> 4;
            const int r0 = rg * 8, cA = jg * 4;
            const int jt = cta >> 4, ks = cta & 15;
            const int j0 = jt * 64, kb = 128 + ks * 40;
            u64 acc[4][4];
            #pragma unroll
            for (int i = 0; i < 4; i++)
                #pragma unroll
                for (int c = 0; c < 4; c++) acc[i][c] = 0ull;
            for (int kc = 0; kc < 40; kc += 20) {
                #pragma unroll
                for (int i = 0; i < 10; i++) {
                    int lin = i * 256 + tid;
                    int kk = lin >> 7, b = lin & 127;
                    xs[kk * 128 + b] = g_xT[(kb + kc + kk) * BB + b];
                }
                #pragma unroll
                for (int i = 0; i < 5; i++) {
                    int lin = i * 256 + tid;
                    int kk = lin >> 6, j = lin & 63;
                    ws[kk * 64 + j] = g_W2e[(size_t)(kb - 128 + kc + kk) * G2 + j0 + j];
                }
                __syncthreads();
                #pragma unroll
                for (int kk = 0; kk < 20; kk++) {
                    ulonglong2 xa = *(const ulonglong2*)&xs[kk * 128 + r0];
                    ulonglong2 xb = *(const ulonglong2*)&xs[kk * 128 + r0 + 4];
                    float4 wA = *(const float4*)&ws[kk * 64 + cA];
                    u64 w[4] = {pack2(wA.x), pack2(wA.y), pack2(wA.z), pack2(wA.w)};
                    u64 xr[4] = {xa.x, xa.y, xb.x, xb.y};
                    #pragma unroll
                    for (int i = 0; i < 4; i++)
                        #pragma unroll
                        for (int c = 0; c < 4; c++) acc[i][c] = ffma2(xr[i], w[c], acc[i][c]);
                }
                __syncthreads();
            }
            float* dst = g_part2[ks];
            #pragma unroll
            for (int c = 0; c < 4; c++) {
                *(ulonglong2*)&dst[(size_t)(j0 + cA + c) * BB + r0]     = make_ulonglong2(acc[0][c], acc[1][c]);
                *(ulonglong2*)&dst[(size_t)(j0 + cA + c) * BB + r0 + 4] = make_ulonglong2(acc[2][c], acc[3][c]);
            }
        }
        gridbar(cta, tid, epoch);

        // ---- Stage C: per-batch CTA: LSTM2 cell, q, attention, context, logits ----
        {
            const int b = cta;
            float* sg   = sh;            // 512
            float* h2s  = sh + 512;      // 128
            float* qs   = sh + 640;      // 128 (reused as ctx)
            float* satt = sh + 768;      // 400
            float* red  = sh + 1200;     // 256
            float* cred = sh + 1456;     // 256
            float* sinv = sh + 1712;     // 1

            #pragma unroll
            for (int e = 0; e < 2; e++) {
                int j = e * 256 + tid;
                float s = g_b2[j];
                #pragma unroll
                for (int ks = 0; ks < 16; ks++) s += g_part2[ks][(size_t)j * BB + b];
                sg[j] = s;
            }
            __syncthreads();
            if (tid < H2) {
                int h = tid;
                float c = sigf(sg[128 + h]) * g_c2[b * H2 + h] + sigf(sg[h]) * tanhf(sg[256 + h]);
                g_c2[b * H2 + h] = c;
                float hh = sigf(sg[384 + h]) * tanhf(c);
                g_xT[(640 + h) * BB + b] = hh;   // h2prev for next step
                h2s[h] = hh;
            }
            __syncthreads();
            if (tid < PP) {
                const float* wr = Wq + tid * H2;
                float s = bq[tid];
                for (int k = 0; k < H2; k++) s += h2s[k] * wr[k];
                qs[tid] = s;
            }
            __syncthreads();
            int lenb = lens[b];
            const float scale = 0.08838834764831845f;   // 1/sqrt(128)
            float pmax = -3.4e38f;
            for (int s = tid; s < SS; s += NTHR) {
                const float4* kr = (const float4*)(g_keys + ((size_t)b * SS + s) * PP);
                const float4* q4 = (const float4*)qs;
                float d = 0.f;
                #pragma unroll 8
                for (int p4 = 0; p4 < 32; p4++) {
                    float4 kv = kr[p4], qv = q4[p4];
                    d += kv.x*qv.x + kv.y*qv.y + kv.z*qv.z + kv.w*qv.w;
                }
                d *= scale;
                if (s >= lenb) d = -1e9f;
                satt[s] = d;
                pmax = fmaxf(pmax, d);
            }
            red[tid] = pmax; __syncthreads();
            for (int o = 128; o > 0; o >>= 1) {
                if (tid < o) red[tid] = fmaxf(red[tid], red[tid + o]);
                __syncthreads();
            }
            float mx = red[0];
            __syncthreads();
            float psum = 0.f;
            for (int s = tid; s < SS; s += NTHR) {
                float e = expf(satt[s] - mx);
                satt[s] = e;
                psum += e;
            }
            red[tid] = psum; __syncthreads();
            for (int o = 128; o > 0; o >>= 1) {
                if (tid < o) red[tid] += red[tid + o];
                __syncthreads();
            }
            if (tid == 0) sinv[0] = 1.f / red[0];
            __syncthreads();
            float inv = sinv[0];
            {
                int p = tid & 127, half = tid >> 7;
                float c = 0.f;
                int s0 = half * 200;
                for (int s = s0; s < s0 + 200; s++)
                    c += satt[s] * g_values[((size_t)b * SS + s) * PP + p];
                cred[tid] = c;
            }
            __syncthreads();
            if (tid < PP) {
                float c = (cred[tid] + cred[tid + 128]) * inv;
                g_xT[tid * BB + b] = c;   // ctx for next step
                qs[tid] = c;
            }
            __syncthreads();
            if (tid < VV) {
                const float* er = emb + tid * EMBD;
                float lg = bout[tid];
                for (int e = 0; e < 128; e++) lg += qs[e] * er[e] + h2s[e] * er[128 + e];
                out[((size_t)b * VV + tid) * TT + t] = lg;   // predictions [B,V,T]
            }
            if (b == 0) {
                for (int s = tid; s < SS; s += NTHR)
                    out[PRED_N + t * SS + s] = satt[s] * inv;  // attention_plot [T,S]
            }
        }
        gridbar(cta, tid, epoch);
    }
}

// ---------------- launch ----------------
extern "C" void kernel_launch(void* const* d_in, const int* in_sizes, int n_in,
                              void* d_out, int out_size) {
    (void)in_sizes; (void)n_in; (void)out_size;
    const float* enc  = (const float*)d_in[0];
    const int*   lens = (const int*)d_in[1];
    const int*   y    = (const int*)d_in[2];
    const float* emb  = (const float*)d_in[3];
    const float* Wih1 = (const float*)d_in[4];
    const float* Whh1 = (const float*)d_in[5];
    const float* bih1 = (const float*)d_in[6];
    const float* bhh1 = (const float*)d_in[7];
    const float* Wih2 = (const float*)d_in[8];
    const float* Whh2 = (const float*)d_in[9];
    const float* bih2 = (const float*)d_in[10];
    const float* bhh2 = (const float*)d_in[11];
    const float* Wk   = (const float*)d_in[12];
    const float* bk   = (const float*)d_in[13];
    const float* Wv   = (const float*)d_in[14];
    const float* bv   = (const float*)d_in[15];
    const float* Wq   = (const float*)d_in[16];
    const float* bq   = (const float*)d_in[17];
    const float* bout = (const float*)d_in[18];
    float* out = (float*)d_out;

    int pack_n = 640 * G1 + 640 * G2 + G2;
    pack_kernel<<<(pack_n + 255) / 256, 256>>>(Wih1, Whh1, Wih2, Whh2, bih2, bhh2);
    memb_kernel<<<(VV * G1 + 255) / 256, 256>>>(emb, Wih1, bih1, bhh1);
    kv_kernel<<<dim3(400, 8), 256>>>(enc, Wk, bk, Wv, bv);
    init_kernel<<<320, 256>>>();
    loop_kernel<<<NCTA, NTHR>>>(y, lens, Wq, bq, emb, bout, out);
}